// round 12
// baseline (speedup 1.0000x reference)
#include <cuda_runtime.h>
#include <cuda_bf16.h>
#include <cstdint>

// Problem constants
#define TSTEPS   200
#define UDIM     128
#define BATCH    2048
#define MROWS    (BATCH * TSTEPS)     // 409600
#define GSTRIDE  384                  // xr|xz|xh concatenated
#define INSTRIDE 129                  // inputs last dim = U+1

// Scratch for precomputed input projections: 409600 x 384 fp32 = 629 MB
__device__ float g_G[157286400];      // MROWS * GSTRIDE

// Pre-split W fragments: [gate][hi 32KB | lo 32KB] in mma frag layout
__device__ __align__(16) unsigned char g_Wfrag[3 * 65536];

typedef unsigned long long ull;

// ---------------- fast activations ----------------
__device__ __forceinline__ float sigf(float x) {
    return __fdividef(1.0f, 1.0f + __expf(-x));
}
__device__ __forceinline__ float tanhfast(float x) {
    float e = __expf(-2.0f * fabsf(x));
    float t = __fdividef(1.0f - e, 1.0f + e);
    return copysignf(t, x);
}

// ---------------- cp.async helpers ----------------
__device__ __forceinline__ void cpa16(uint32_t saddr, const void* g) {
    asm volatile("cp.async.ca.shared.global [%0], [%1], 16;" :: "r"(saddr), "l"(g));
}
__device__ __forceinline__ void cpa4(uint32_t saddr, const void* g) {
    asm volatile("cp.async.ca.shared.global [%0], [%1], 4;" :: "r"(saddr), "l"(g));
}
__device__ __forceinline__ void cpa_commit() { asm volatile("cp.async.commit_group;"); }
__device__ __forceinline__ void cpa_wait0()  { asm volatile("cp.async.wait_group 0;"); }
__device__ __forceinline__ void cpa_wait1()  { asm volatile("cp.async.wait_group 1;"); }

// ---------------- mma.sync helpers ----------------
__device__ __forceinline__ void mma16816(float* c, const uint32_t* a, const uint32_t* b) {
    asm volatile(
        "mma.sync.aligned.m16n8k16.row.col.f32.bf16.bf16.f32 "
        "{%0,%1,%2,%3}, {%4,%5,%6,%7}, {%8,%9}, {%0,%1,%2,%3};"
        : "+f"(c[0]), "+f"(c[1]), "+f"(c[2]), "+f"(c[3])
        : "r"(a[0]), "r"(a[1]), "r"(a[2]), "r"(a[3]), "r"(b[0]), "r"(b[1]));
}
__device__ __forceinline__ void lds128(uint32_t* r, uint32_t addr) {
    asm volatile("ld.shared.v4.u32 {%0,%1,%2,%3}, [%4];"
        : "=r"(r[0]), "=r"(r[1]), "=r"(r[2]), "=r"(r[3]) : "r"(addr));
}
__device__ __forceinline__ void lds64(uint32_t* r, uint32_t addr) {
    asm volatile("ld.shared.v2.u32 {%0,%1}, [%2];"
        : "=r"(r[0]), "=r"(r[1]) : "r"(addr));
}
__device__ __forceinline__ void sts32(uint32_t addr, uint32_t v) {
    asm volatile("st.shared.u32 [%0], %1;" :: "r"(addr), "r"(v));
}
__device__ __forceinline__ void sts64f(uint32_t addr, float x, float y) {
    asm volatile("st.shared.v2.f32 [%0], {%1,%2};" :: "r"(addr), "f"(x), "f"(y));
}
// Split packed pair (x0, x1) into bf16x2 hi and lo parts. lo half of reg = x0.
__device__ __forceinline__ void split2(float x0, float x1, uint32_t& hi, uint32_t& lo) {
    asm("cvt.rn.bf16x2.f32 %0, %1, %2;" : "=r"(hi) : "f"(x1), "f"(x0));
    float h0 = __uint_as_float(hi << 16);
    float h1 = __uint_as_float(hi & 0xFFFF0000u);
    float l0 = x0 - h0;
    float l1 = x1 - h1;
    asm("cvt.rn.bf16x2.f32 %0, %1, %2;" : "=r"(lo) : "f"(l1), "f"(l0));
}

// =====================================================================
// Prep: split W matrices into mma B-fragment layout (bf16 hi/lo) once.
// Layout identical to the R6 in-kernel W split:
//   off = ((nfrag*8+ks)<<8) + ((nn*4+(kp&3))<<3) + (chi<<2)
// =====================================================================
__global__ void prep_w(const float* __restrict__ Wr,
                       const float* __restrict__ Wz,
                       const float* __restrict__ Wh)
{
    const int g = blockIdx.x;
    const float* Wg = (g == 0) ? Wr : (g == 1) ? Wz : Wh;
    unsigned char* dsth = g_Wfrag + g * 65536;
    unsigned char* dstl = dsth + 32768;
    for (int idx = threadIdx.x; idx < 128 * 64; idx += blockDim.x) {
        int n = idx >> 6, kp = idx & 63;
        float w0 = Wg[(2 * kp) * UDIM + n];
        float w1 = Wg[(2 * kp + 1) * UDIM + n];
        uint32_t hi, lo;
        split2(w0, w1, hi, lo);
        int nfrag = n >> 3, nn = n & 7, ks = kp >> 3, chi = (kp >> 2) & 1;
        uint32_t off = (uint32_t)((nfrag * 8 + ks) << 8) + ((nn * 4 + (kp & 3)) << 3) + (chi << 2);
        *(uint32_t*)(dsth + off) = hi;
        *(uint32_t*)(dstl + off) = lo;
    }
}

// =====================================================================
// Stage 1 (R9): CTA owns m-tiles across ALL 3 gates. A-frags built once
// per m-tile (X read once, not 3x). B-frags streamed from pre-split
// L2-hot scratch via cp.async, double-buffered so the load of gate g+1
// overlaps gate g's HMMA mainloop. Mainloop identical to R6 (452us).
// =====================================================================
#define OFF_AHI  0
#define OFF_ALO  32768
#define OFF_B0   65536                 // hi at +0, lo at +32768
#define OFF_B1   131072
#define OFF_BIAS 196608                // 384 floats
#define GM_SMEM  (196608 + 1536)       // 198144 bytes

__global__ void __launch_bounds__(256, 1) gemm_tc(
    const float* __restrict__ inp,
    const float* __restrict__ br, const float* __restrict__ bz, const float* __restrict__ bh)
{
    extern __shared__ __align__(16) char smem[];
    const uint32_t sb = (uint32_t)__cvta_generic_to_shared(smem);
    float* bias_s = (float*)(smem + OFF_BIAS);

    const int tid  = threadIdx.x;
    const int wid  = tid >> 5;
    const int lane = tid & 31;
    const int wm   = wid >> 1;            // 0..3 : 32-row block
    const int wn   = wid & 1;             // 0..1 : 64-col block

    // biases once
    if (tid < 128) {
        bias_s[tid]       = br[tid];
        bias_s[128 + tid] = bz[tid];
        bias_s[256 + tid] = bh[tid];
    }

    // prologue: prefetch gate0 B-frags into buf0
    for (int i = tid; i < 4096; i += 256)
        cpa16(sb + OFF_B0 + i * 16, g_Wfrag + i * 16);
    cpa_commit();

    const int eg  = lane >> 2;
    const int et2 = (lane & 3) * 2;
    int qb = 0;   // parity: buffer holding the CURRENT gate's frags

    for (int mt = blockIdx.x; mt < 3200; mt += 148) {
        const size_t m0 = (size_t)mt * 128;

        // ---- convert X (direct LDG) into A-fragment layout, once per m-tile ----
        {
            const int rbase = tid >> 6;
            const int kp    = tid & 63;
            const int ks  = kp >> 3;
            const int t   = kp & 3;
            const int chi = (kp >> 2) & 1;
            #pragma unroll 4
            for (int j = 0; j < 32; j++) {
                int m = j * 4 + rbase;
                const float* p = inp + (m0 + m) * INSTRIDE + 2 * kp;
                float x0 = p[0];
                float x1 = p[1];
                uint32_t hi, lo;
                split2(x0, x1, hi, lo);
                int mfrag = m >> 4, r = m & 15, g2 = r & 7, rh = r >> 3;
                int lane_sw = (g2 * 4 + t) ^ ((ks & 3) << 1);
                uint32_t off = (uint32_t)((mfrag * 8 + ks) << 9) + (lane_sw << 4) + ((chi * 2 + rh) << 2);
                sts32(sb + OFF_AHI + off, hi);
                sts32(sb + OFF_ALO + off, lo);
            }
        }

        #pragma unroll 1
        for (int g = 0; g < 3; g++) {
            // prefetch NEXT gate's B-frags into the other buffer
            {
                int ng = (g + 1) % 3;
                uint32_t nb = sb + (qb ? OFF_B0 : OFF_B1);
                for (int i = tid; i < 4096; i += 256)
                    cpa16(nb + i * 16, g_Wfrag + ng * 65536 + i * 16);
                cpa_commit();
            }
            cpa_wait1();        // current gate's buffer complete
            __syncthreads();    // A-frags + current B visible to all

            const uint32_t cb = sb + (qb ? OFF_B1 : OFF_B0);

            // ---- mma mainloop (identical structure to R6) ----
            float acc[2][8][4];
            #pragma unroll
            for (int mf = 0; mf < 2; mf++)
                #pragma unroll
                for (int nf = 0; nf < 8; nf++)
                    #pragma unroll
                    for (int q = 0; q < 4; q++) acc[mf][nf][q] = 0.0f;

            #pragma unroll 2
            for (int ks = 0; ks < 8; ks++) {
                const uint32_t asw = (uint32_t)((lane ^ ((ks & 3) << 1)) << 4);
                uint32_t Ahi[2][4], Alo[2][4];
                #pragma unroll
                for (int mf = 0; mf < 2; mf++) {
                    uint32_t blk = (uint32_t)(((wm * 2 + mf) * 8 + ks) << 9) + asw;
                    lds128(Ahi[mf], sb + OFF_AHI + blk);
                    lds128(Alo[mf], sb + OFF_ALO + blk);
                }
                #pragma unroll
                for (int nf = 0; nf < 8; nf++) {
                    uint32_t blk = (uint32_t)(((wn * 8 + nf) * 8 + ks) << 8) + (lane << 3);
                    uint32_t Bh[2], Bl[2];
                    lds64(Bh, cb + blk);
                    lds64(Bl, cb + 32768 + blk);
                    #pragma unroll
                    for (int mf = 0; mf < 2; mf++) {
                        mma16816(acc[mf][nf], Ahi[mf], Bh);
                        mma16816(acc[mf][nf], Ahi[mf], Bl);
                        mma16816(acc[mf][nf], Alo[mf], Bh);
                    }
                }
            }

            // ---- epilogue: direct STG.64 ----
            #pragma unroll
            for (int mf = 0; mf < 2; mf++) {
                size_t row = m0 + wm * 32 + mf * 16 + eg;
                #pragma unroll
                for (int nf = 0; nf < 8; nf++) {
                    int coll = wn * 64 + nf * 8 + et2;
                    float b0 = bias_s[g * 128 + coll], b1 = bias_s[g * 128 + coll + 1];
                    float* gp = g_G + row * GSTRIDE + g * 128 + coll;
                    float2 v0 = make_float2(acc[mf][nf][0] + b0, acc[mf][nf][1] + b1);
                    float2 v1 = make_float2(acc[mf][nf][2] + b0, acc[mf][nf][3] + b1);
                    *(float2*)gp = v0;
                    *(float2*)(gp + 8 * GSTRIDE) = v1;
                }
            }
            qb ^= 1;
            __syncthreads();    // mainloop reads done before buffer/A-frag reuse
        }
    }
}

// =====================================================================
// Stage 2: tensor-core recurrence (unchanged, measured 488us).
// =====================================================================
#define OFF2_BLO  0                    // 48 nfrags x 8 ks x 256B = 98304
#define OFF2_AFH  98304                // 8 ks x 32 lanes x 16B = 4096
#define OFF2_AFL  102400               // 4096
#define OFF2_ACC  106496               // 3*16*132*4 = 25344
#define OFF2_GXS  131840               // 14*384*4 = 21504
#define OFF2_AS   153344               // 64
#define SMEM2     153408

__device__ __forceinline__ uint32_t afrag_off(int r, int u2) {
    int ks   = u2 >> 4;
    int lane = ((r & 7) << 2) | ((u2 >> 1) & 3);
    int reg  = (r >> 3) | (((u2 >> 3) & 1) << 1);
    return (uint32_t)(ks * 512 + lane * 16 + reg * 4);
}

__global__ void __launch_bounds__(384, 1) gru_recur(
    const float* __restrict__ inp,
    const float* __restrict__ h0,
    const float* __restrict__ Ur, const float* __restrict__ Uz, const float* __restrict__ Uh,
    float* __restrict__ out)
{
    extern __shared__ __align__(16) char smem2[];
    const uint32_t sb = (uint32_t)__cvta_generic_to_shared(smem2);
    float* gxs  = (float*)(smem2 + OFF2_GXS);
    float* as_s = (float*)(smem2 + OFF2_AS);
    float* accs = (float*)(smem2 + OFF2_ACC);

    const int tid  = threadIdx.x;
    const int wid  = tid >> 5;
    const int lane = tid & 31;

    // Balanced row partition over 148 CTAs: 124x14 + 24x13 = 2048
    const int bid = blockIdx.x;
    int row0, cnt;
    if (bid < 124) { row0 = bid * 14;                    cnt = 14; }
    else           { row0 = 124 * 14 + (bid - 124) * 13; cnt = 13; }

    // zero A-frag regions (covers padded rows cnt..15 forever)
    for (int i = tid; i < 1024; i += 384) {
        ((uint32_t*)(smem2 + OFF2_AFH))[i] = 0;
        ((uint32_t*)(smem2 + OFF2_AFL))[i] = 0;
    }

    // ---- build B (U-cat) hi parts in frag layout ----
    for (int idx = tid; idx < 384 * 64; idx += 384) {
        int n = idx >> 6, kp = idx & 63;
        int g = n >> 7, col = n & 127;
        const float* Ug = (g == 0) ? Ur : (g == 1) ? Uz : Uh;
        float w0 = Ug[(2 * kp) * UDIM + col];
        float w1 = Ug[(2 * kp + 1) * UDIM + col];
        uint32_t hi, lo;
        split2(w0, w1, hi, lo);
        int nf48 = n >> 3, nn = n & 7, ks = kp >> 3, chi = (kp >> 2) & 1;
        uint32_t off = ((uint32_t)(nf48 * 8 + ks) << 8) + ((nn * 4 + (kp & 3)) << 3) + (chi << 2);
        sts32(sb + OFF2_BLO + off, hi);
    }
    __syncthreads();

    // each warp loads its resident B-hi fragments (64 regs)
    uint32_t bhi[4][8][2];
    #pragma unroll
    for (int nf = 0; nf < 4; nf++)
        #pragma unroll
        for (int ks = 0; ks < 8; ks++)
            lds64(bhi[nf][ks],
                  sb + OFF2_BLO + (((uint32_t)((wid * 4 + nf) * 8 + ks)) << 8) + (lane << 3));
    __syncthreads();

    // ---- overwrite B region with lo parts ----
    for (int idx = tid; idx < 384 * 64; idx += 384) {
        int n = idx >> 6, kp = idx & 63;
        int g = n >> 7, col = n & 127;
        const float* Ug = (g == 0) ? Ur : (g == 1) ? Uz : Uh;
        float w0 = Ug[(2 * kp) * UDIM + col];
        float w1 = Ug[(2 * kp + 1) * UDIM + col];
        uint32_t hi, lo;
        split2(w0, w1, hi, lo);
        int nf48 = n >> 3, nn = n & 7, ks = kp >> 3, chi = (kp >> 2) & 1;
        uint32_t off = ((uint32_t)(nf48 * 8 + ks) << 8) + ((nn * 4 + (kp & 3)) << 3) + (chi << 2);
        sts32(sb + OFF2_BLO + off, lo);
    }

    // ---- h state -> registers; initial A-frag from h0 ----
    float2 hreg[3];
    #pragma unroll
    for (int i = 0; i < 3; i++) {
        int p = tid + i * 384;
        if (p < cnt * 64) {
            int r = p >> 6, u2 = (p & 63) << 1;
            hreg[i] = *(const float2*)(h0 + (size_t)(row0 + r) * UDIM + u2);
            uint32_t hi, lo;
            split2(hreg[i].x, hreg[i].y, hi, lo);
            uint32_t o = afrag_off(r, u2);
            sts32(sb + OFF2_AFH + o, hi);
            sts32(sb + OFF2_AFL + o, lo);
        }
    }
    __syncthreads();

    // B-lo fragments for nfrags 0-1 -> registers (reads lo parts, post-sync)
    uint32_t blor[2][8][2];
    #pragma unroll
    for (int nf = 0; nf < 2; nf++)
        #pragma unroll
        for (int ks = 0; ks < 8; ks++)
            lds64(blor[nf][ks],
                  sb + OFF2_BLO + (((uint32_t)((wid * 4 + nf) * 8 + ks)) << 8) + (lane << 3));

    const int gate = wid >> 2;
    const int colb = ((wid & 3) << 5) + ((lane & 3) << 1);
    const int r1   = lane >> 2;

    for (int t = 0; t < TSTEPS; t++) {
        // ---- prefetch this step's pointwise operands ----
        {
            int nchunks = cnt * 96;
            for (int i = tid; i < nchunks; i += 384) {
                int rr = i / 96, q = i - rr * 96;
                size_t base = (size_t)(row0 + rr) * TSTEPS + t;
                cpa16(sb + OFF2_GXS + (uint32_t)(rr * GSTRIDE + q * 4) * 4,
                      g_G + base * GSTRIDE + q * 4);
            }
            if (tid < cnt) {
                size_t base = (size_t)(row0 + tid) * TSTEPS + t;
                cpa4(sb + OFF2_AS + tid * 4, inp + base * INSTRIDE + UDIM);
            }
            cpa_commit();
        }

        // ---- MMA phase: acc[16 x 32cols] = h @ U (3-pass split) ----
        float acc[4][4];
        #pragma unroll
        for (int nf = 0; nf < 4; nf++)
            #pragma unroll
            for (int q = 0; q < 4; q++) acc[nf][q] = 0.0f;

        #pragma unroll
        for (int ks = 0; ks < 8; ks++) {
            uint32_t Ah[4], Al[4];
            lds128(Ah, sb + OFF2_AFH + ks * 512 + lane * 16);
            lds128(Al, sb + OFF2_AFL + ks * 512 + lane * 16);
            #pragma unroll
            for (int nf = 0; nf < 2; nf++) {
                mma16816(acc[nf], Ah, bhi[nf][ks]);
                mma16816(acc[nf], Ah, blor[nf][ks]);
                mma16816(acc[nf], Al, bhi[nf][ks]);
            }
            #pragma unroll
            for (int nf = 2; nf < 4; nf++) {
                uint32_t Bl[2];
                lds64(Bl, sb + OFF2_BLO + (((uint32_t)((wid * 4 + nf) * 8 + ks)) << 8) + (lane << 3));
                mma16816(acc[nf], Ah, bhi[nf][ks]);
                mma16816(acc[nf], Ah, Bl);
                mma16816(acc[nf], Al, bhi[nf][ks]);
            }
        }

        // ---- scatter accs to smem (padded stride 132) ----
        #pragma unroll
        for (int nf = 0; nf < 4; nf++) {
            int colg = colb + (nf << 3);
            sts64f(sb + OFF2_ACC + (uint32_t)((gate * 16 + r1) * 132 + colg) * 4,
                   acc[nf][0], acc[nf][1]);
            sts64f(sb + OFF2_ACC + (uint32_t)((gate * 16 + r1 + 8) * 132 + colg) * 4,
                   acc[nf][2], acc[nf][3]);
        }
        cpa_wait0();
        __syncthreads();

        // ---- pointwise GRU update; h in regs; writes out + next A-frag ----
        #pragma unroll
        for (int i = 0; i < 3; i++) {
            int p = tid + i * 384;
            if (p < cnt * 64) {
                int r = p >> 6, u2 = (p & 63) << 1;
                size_t base = (size_t)(row0 + r) * TSTEPS + t;
                float2 xr = *(float2*)(gxs + r * GSTRIDE + u2);
                float2 xz = *(float2*)(gxs + r * GSTRIDE + UDIM + u2);
                float2 xh = *(float2*)(gxs + r * GSTRIDE + 2 * UDIM + u2);
                float  a  = as_s[r];
                float2 hp = hreg[i];

                float ar0 = accs[(r)      * 132 + u2], ar1 = accs[(r)      * 132 + u2 + 1];
                float az0 = accs[(16 + r) * 132 + u2], az1 = accs[(16 + r) * 132 + u2 + 1];
                float ah0 = accs[(32 + r) * 132 + u2], ah1 = accs[(32 + r) * 132 + u2 + 1];

                float rv0 = sigf(xr.x + ar0), rv1 = sigf(xr.y + ar1);
                float zv0 = sigf(xz.x + az0), zv1 = sigf(xz.y + az1);
                float ht0 = tanhfast(xh.x + rv0 * ah0);
                float ht1 = tanhfast(xh.y + rv1 * ah1);
                float u0 = a * zv0, u1 = a * zv1;
                float hn0 = (1.0f - u0) * hp.x + u0 * ht0;
                float hn1 = (1.0f - u1) * hp.y + u1 * ht1;

                *(float2*)(out + base * UDIM + u2) = make_float2(hn0, hn1);
                hreg[i] = make_float2(hn0, hn1);

                uint32_t hi, lo;
                split2(hn0, hn1, hi, lo);
                uint32_t o = afrag_off(r, u2);
                sts32(sb + OFF2_AFH + o, hi);
                sts32(sb + OFF2_AFL + o, lo);
            }
        }
        __syncthreads();
    }
}

// =====================================================================
// Launch
// Inputs (metadata order): inputs, h0, W_r, U_r, b_r, W_z, U_z, b_z, W_h, U_h, b_h
// =====================================================================
extern "C" void kernel_launch(void* const* d_in, const int* in_sizes, int n_in,
                              void* d_out, int out_size)
{
    const float* inp = (const float*)d_in[0];
    const float* h0  = (const float*)d_in[1];
    const float* Wr  = (const float*)d_in[2];
    const float* Ur  = (const float*)d_in[3];
    const float* br  = (const float*)d_in[4];
    const float* Wz  = (const float*)d_in[5];
    const float* Uz  = (const float*)d_in[6];
    const float* bz  = (const float*)d_in[7];
    const float* Wh  = (const float*)d_in[8];
    const float* Uh  = (const float*)d_in[9];
    const float* bh  = (const float*)d_in[10];
    float* out = (float*)d_out;

    cudaFuncSetAttribute(gemm_tc, cudaFuncAttributeMaxDynamicSharedMemorySize, GM_SMEM);
    cudaFuncSetAttribute(gru_recur, cudaFuncAttributeMaxDynamicSharedMemorySize, SMEM2);

    prep_w<<<3, 256>>>(Wr, Wz, Wh);
    gemm_tc<<<148, 256, GM_SMEM>>>(inp, br, bz, bh);
    gru_recur<<<148, 384, SMEM2>>>(inp, h0, Ur, Uz, Uh, out);
}

// round 13
// speedup vs baseline: 1.5463x; 1.5463x over previous
#include <cuda_runtime.h>
#include <cuda_bf16.h>
#include <cstdint>

// Problem constants
#define TSTEPS   200
#define UDIM     128
#define BATCH    2048
#define MROWS    (BATCH * TSTEPS)     // 409600
#define GSTRIDE  384                  // xr|xz|xh concatenated
#define INSTRIDE 129                  // inputs last dim = U+1

// Scratch for precomputed input projections: 409600 x 384 fp32 = 629 MB
__device__ float g_G[157286400];      // MROWS * GSTRIDE

typedef unsigned long long ull;

// ---------------- fast activations ----------------
__device__ __forceinline__ float sigf(float x) {
    return __fdividef(1.0f, 1.0f + __expf(-x));
}
__device__ __forceinline__ float tanhfast(float x) {
    float e = __expf(-2.0f * fabsf(x));
    float t = __fdividef(1.0f - e, 1.0f + e);
    return copysignf(t, x);
}

// ---------------- cp.async helpers ----------------
__device__ __forceinline__ void cpa16(uint32_t saddr, const void* g) {
    asm volatile("cp.async.ca.shared.global [%0], [%1], 16;" :: "r"(saddr), "l"(g));
}
__device__ __forceinline__ void cpa4(uint32_t saddr, const void* g) {
    asm volatile("cp.async.ca.shared.global [%0], [%1], 4;" :: "r"(saddr), "l"(g));
}
__device__ __forceinline__ void cpa_commit() { asm volatile("cp.async.commit_group;"); }
__device__ __forceinline__ void cpa_wait0()  { asm volatile("cp.async.wait_group 0;"); }

// ---------------- mma.sync helpers ----------------
__device__ __forceinline__ void mma16816(float* c, const uint32_t* a, const uint32_t* b) {
    asm volatile(
        "mma.sync.aligned.m16n8k16.row.col.f32.bf16.bf16.f32 "
        "{%0,%1,%2,%3}, {%4,%5,%6,%7}, {%8,%9}, {%0,%1,%2,%3};"
        : "+f"(c[0]), "+f"(c[1]), "+f"(c[2]), "+f"(c[3])
        : "r"(a[0]), "r"(a[1]), "r"(a[2]), "r"(a[3]), "r"(b[0]), "r"(b[1]));
}
__device__ __forceinline__ void lds128(uint32_t* r, uint32_t addr) {
    asm volatile("ld.shared.v4.u32 {%0,%1,%2,%3}, [%4];"
        : "=r"(r[0]), "=r"(r[1]), "=r"(r[2]), "=r"(r[3]) : "r"(addr));
}
__device__ __forceinline__ void lds64(uint32_t* r, uint32_t addr) {
    asm volatile("ld.shared.v2.u32 {%0,%1}, [%2];"
        : "=r"(r[0]), "=r"(r[1]) : "r"(addr));
}
__device__ __forceinline__ void sts32(uint32_t addr, uint32_t v) {
    asm volatile("st.shared.u32 [%0], %1;" :: "r"(addr), "r"(v));
}
__device__ __forceinline__ void sts64f(uint32_t addr, float x, float y) {
    asm volatile("st.shared.v2.f32 [%0], {%1,%2};" :: "r"(addr), "f"(x), "f"(y));
}
// Split packed pair (x0, x1) into bf16x2 hi and lo parts. lo half of reg = x0.
__device__ __forceinline__ void split2(float x0, float x1, uint32_t& hi, uint32_t& lo) {
    asm("cvt.rn.bf16x2.f32 %0, %1, %2;" : "=r"(hi) : "f"(x1), "f"(x0));
    float h0 = __uint_as_float(hi << 16);
    float h1 = __uint_as_float(hi & 0xFFFF0000u);
    float l0 = x0 - h0;
    float l1 = x1 - h1;
    asm("cvt.rn.bf16x2.f32 %0, %1, %2;" : "=r"(lo) : "f"(l1), "f"(l0));
}

// =====================================================================
// Stage 1: EXACT R6 gemm (measured 452us as part of the 942us total).
// G[m][n] = X[m][:] . Wcat[:][n] + bias, mma.sync bf16 3-pass split.
// M-tile 128, N-tile 128 (one gate per CTA), K=128. cp.async (cpa4)
// raw-X staging pipelined against the HMMA mainloop.
// =====================================================================
#define OFF_AHI  0
#define OFF_ALO  32768
#define OFF_BHI  65536
#define OFF_BLO  98304
#define OFF_BIAS 131072
#define OFF_RAW  131584
#define GM_SMEM  (OFF_RAW + 65536)    // 197120 bytes

__global__ void __launch_bounds__(256, 1) gemm_tc(
    const float* __restrict__ inp,
    const float* __restrict__ Wr, const float* __restrict__ Wz, const float* __restrict__ Wh,
    const float* __restrict__ br, const float* __restrict__ bz, const float* __restrict__ bh)
{
    extern __shared__ __align__(16) char smem[];
    const uint32_t sb = (uint32_t)__cvta_generic_to_shared(smem);
    float* bias_s = (float*)(smem + OFF_BIAS);
    const float* raws = (const float*)(smem + OFF_RAW);

    const int tid  = threadIdx.x;
    const int wid  = tid >> 5;
    const int lane = tid & 31;
    const int wm   = wid >> 1;
    const int wn   = wid & 1;

    const int bid   = blockIdx.x;
    const int nblk  = bid % 3;
    const int start = bid / 3;
    const int mstride = (nblk == 0) ? 50 : 49;

    const float* Wg   = (nblk == 0) ? Wr : (nblk == 1) ? Wz : Wh;
    const float* bsrc = (nblk == 0) ? br : (nblk == 1) ? bz : bh;

    // ---- load + split W into B-fragment layout (once per CTA) ----
    {
        const int rbase = tid >> 6;
        const int kp    = tid & 63;
        const int ks  = kp >> 3;
        const int chi = (kp >> 2) & 1;
        #pragma unroll 4
        for (int j = 0; j < 32; j++) {
            int n = j * 4 + rbase;
            float w0 = Wg[(2 * kp) * UDIM + n];
            float w1 = Wg[(2 * kp + 1) * UDIM + n];
            uint32_t hi, lo;
            split2(w0, w1, hi, lo);
            int nfrag = n >> 3, nn = n & 7;
            uint32_t off = (uint32_t)((nfrag * 8 + ks) << 8) + ((nn * 4 + (kp & 3)) << 3) + (chi << 2);
            sts32(sb + OFF_BHI + off, hi);
            sts32(sb + OFF_BLO + off, lo);
        }
        if (tid < 128) bias_s[tid] = bsrc[tid];
    }

    // ---- prologue: prefetch first tile's raw X ----
    if (start < 3200) {
        const size_t m0 = (size_t)start * 128;
        #pragma unroll 8
        for (int j = 0; j < 64; j++) {
            int idx = j * 256 + tid;
            int row = idx >> 7, col = idx & 127;
            cpa4(sb + OFF_RAW + (uint32_t)idx * 4,
                 inp + (m0 + row) * INSTRIDE + col);
        }
    }
    cpa_commit();

    const int eg  = lane >> 2;
    const int et2 = (lane & 3) * 2;

    for (int mt = start; mt < 3200; mt += mstride) {
        const size_t m0 = (size_t)mt * 128;

        cpa_wait0();
        __syncthreads();

        // ---- convert raw X (smem) into A-fragment layout ----
        {
            const int rbase = tid >> 6;
            const int kp    = tid & 63;
            const int ks  = kp >> 3;
            const int t   = kp & 3;
            const int chi = (kp >> 2) & 1;
            #pragma unroll 4
            for (int j = 0; j < 32; j++) {
                int m = j * 4 + rbase;
                float2 x = *(const float2*)(raws + m * 128 + 2 * kp);
                uint32_t hi, lo;
                split2(x.x, x.y, hi, lo);
                int mfrag = m >> 4, r = m & 15, g2 = r & 7, rh = r >> 3;
                int lane_sw = (g2 * 4 + t) ^ ((ks & 3) << 1);
                uint32_t off = (uint32_t)((mfrag * 8 + ks) << 9) + (lane_sw << 4) + ((chi * 2 + rh) << 2);
                sts32(sb + OFF_AHI + off, hi);
                sts32(sb + OFF_ALO + off, lo);
            }
        }
        __syncthreads();

        // ---- prefetch next tile's raw X (overlaps mainloop) ----
        {
            int nmt = mt + mstride;
            if (nmt < 3200) {
                const size_t nm0 = (size_t)nmt * 128;
                #pragma unroll 8
                for (int j = 0; j < 64; j++) {
                    int idx = j * 256 + tid;
                    int row = idx >> 7, col = idx & 127;
                    cpa4(sb + OFF_RAW + (uint32_t)idx * 4,
                         inp + (nm0 + row) * INSTRIDE + col);
                }
            }
            cpa_commit();
        }

        // ---- mma mainloop ----
        float acc[2][8][4];
        #pragma unroll
        for (int mf = 0; mf < 2; mf++)
            #pragma unroll
            for (int nf = 0; nf < 8; nf++)
                #pragma unroll
                for (int q = 0; q < 4; q++) acc[mf][nf][q] = 0.0f;

        #pragma unroll 2
        for (int ks = 0; ks < 8; ks++) {
            const uint32_t asw = (uint32_t)((lane ^ ((ks & 3) << 1)) << 4);
            uint32_t Ahi[2][4], Alo[2][4];
            #pragma unroll
            for (int mf = 0; mf < 2; mf++) {
                uint32_t blk = (uint32_t)(((wm * 2 + mf) * 8 + ks) << 9) + asw;
                lds128(Ahi[mf], sb + OFF_AHI + blk);
                lds128(Alo[mf], sb + OFF_ALO + blk);
            }
            uint32_t Bhi[8][2], Blo[8][2];
            #pragma unroll
            for (int nf = 0; nf < 8; nf++) {
                uint32_t blk = (uint32_t)(((wn * 8 + nf) * 8 + ks) << 8) + (lane << 3);
                lds64(Bhi[nf], sb + OFF_BHI + blk);
                lds64(Blo[nf], sb + OFF_BLO + blk);
            }
            #pragma unroll
            for (int mf = 0; mf < 2; mf++)
                #pragma unroll
                for (int nf = 0; nf < 8; nf++) {
                    mma16816(acc[mf][nf], Ahi[mf], Bhi[nf]);
                    mma16816(acc[mf][nf], Ahi[mf], Blo[nf]);
                    mma16816(acc[mf][nf], Alo[mf], Bhi[nf]);
                }
        }

        // ---- epilogue: direct STG.64 ----
        #pragma unroll
        for (int mf = 0; mf < 2; mf++) {
            size_t row = m0 + wm * 32 + mf * 16 + eg;
            #pragma unroll
            for (int nf = 0; nf < 8; nf++) {
                int coll = wn * 64 + nf * 8 + et2;
                float b0 = bias_s[coll], b1 = bias_s[coll + 1];
                float* gp = g_G + row * GSTRIDE + nblk * 128 + coll;
                float2 v0 = make_float2(acc[mf][nf][0] + b0, acc[mf][nf][1] + b1);
                float2 v1 = make_float2(acc[mf][nf][2] + b0, acc[mf][nf][3] + b1);
                *(float2*)gp = v0;
                *(float2*)(gp + 8 * GSTRIDE) = v1;
            }
        }
    }
}

// =====================================================================
// Stage 2: tensor-core recurrence (unchanged, measured 488us).
// =====================================================================
#define OFF2_BLO  0                    // 48 nfrags x 8 ks x 256B = 98304
#define OFF2_AFH  98304                // 8 ks x 32 lanes x 16B = 4096
#define OFF2_AFL  102400               // 4096
#define OFF2_ACC  106496               // 3*16*132*4 = 25344
#define OFF2_GXS  131840               // 14*384*4 = 21504
#define OFF2_AS   153344               // 64
#define SMEM2     153408

__device__ __forceinline__ uint32_t afrag_off(int r, int u2) {
    int ks   = u2 >> 4;
    int lane = ((r & 7) << 2) | ((u2 >> 1) & 3);
    int reg  = (r >> 3) | (((u2 >> 3) & 1) << 1);
    return (uint32_t)(ks * 512 + lane * 16 + reg * 4);
}

__global__ void __launch_bounds__(384, 1) gru_recur(
    const float* __restrict__ inp,
    const float* __restrict__ h0,
    const float* __restrict__ Ur, const float* __restrict__ Uz, const float* __restrict__ Uh,
    float* __restrict__ out)
{
    extern __shared__ __align__(16) char smem2[];
    const uint32_t sb = (uint32_t)__cvta_generic_to_shared(smem2);
    float* gxs  = (float*)(smem2 + OFF2_GXS);
    float* as_s = (float*)(smem2 + OFF2_AS);
    float* accs = (float*)(smem2 + OFF2_ACC);

    const int tid  = threadIdx.x;
    const int wid  = tid >> 5;
    const int lane = tid & 31;

    // Balanced row partition over 148 CTAs: 124x14 + 24x13 = 2048
    const int bid = blockIdx.x;
    int row0, cnt;
    if (bid < 124) { row0 = bid * 14;                    cnt = 14; }
    else           { row0 = 124 * 14 + (bid - 124) * 13; cnt = 13; }

    // zero A-frag regions (covers padded rows cnt..15 forever)
    for (int i = tid; i < 1024; i += 384) {
        ((uint32_t*)(smem2 + OFF2_AFH))[i] = 0;
        ((uint32_t*)(smem2 + OFF2_AFL))[i] = 0;
    }

    // ---- build B (U-cat) hi parts in frag layout ----
    for (int idx = tid; idx < 384 * 64; idx += 384) {
        int n = idx >> 6, kp = idx & 63;
        int g = n >> 7, col = n & 127;
        const float* Ug = (g == 0) ? Ur : (g == 1) ? Uz : Uh;
        float w0 = Ug[(2 * kp) * UDIM + col];
        float w1 = Ug[(2 * kp + 1) * UDIM + col];
        uint32_t hi, lo;
        split2(w0, w1, hi, lo);
        int nf48 = n >> 3, nn = n & 7, ks = kp >> 3, chi = (kp >> 2) & 1;
        uint32_t off = ((uint32_t)(nf48 * 8 + ks) << 8) + ((nn * 4 + (kp & 3)) << 3) + (chi << 2);
        sts32(sb + OFF2_BLO + off, hi);
    }
    __syncthreads();

    // each warp loads its resident B-hi fragments (64 regs)
    uint32_t bhi[4][8][2];
    #pragma unroll
    for (int nf = 0; nf < 4; nf++)
        #pragma unroll
        for (int ks = 0; ks < 8; ks++)
            lds64(bhi[nf][ks],
                  sb + OFF2_BLO + (((uint32_t)((wid * 4 + nf) * 8 + ks)) << 8) + (lane << 3));
    __syncthreads();

    // ---- overwrite B region with lo parts ----
    for (int idx = tid; idx < 384 * 64; idx += 384) {
        int n = idx >> 6, kp = idx & 63;
        int g = n >> 7, col = n & 127;
        const float* Ug = (g == 0) ? Ur : (g == 1) ? Uz : Uh;
        float w0 = Ug[(2 * kp) * UDIM + col];
        float w1 = Ug[(2 * kp + 1) * UDIM + col];
        uint32_t hi, lo;
        split2(w0, w1, hi, lo);
        int nf48 = n >> 3, nn = n & 7, ks = kp >> 3, chi = (kp >> 2) & 1;
        uint32_t off = ((uint32_t)(nf48 * 8 + ks) << 8) + ((nn * 4 + (kp & 3)) << 3) + (chi << 2);
        sts32(sb + OFF2_BLO + off, lo);
    }

    // ---- h state -> registers; initial A-frag from h0 ----
    float2 hreg[3];
    #pragma unroll
    for (int i = 0; i < 3; i++) {
        int p = tid + i * 384;
        if (p < cnt * 64) {
            int r = p >> 6, u2 = (p & 63) << 1;
            hreg[i] = *(const float2*)(h0 + (size_t)(row0 + r) * UDIM + u2);
            uint32_t hi, lo;
            split2(hreg[i].x, hreg[i].y, hi, lo);
            uint32_t o = afrag_off(r, u2);
            sts32(sb + OFF2_AFH + o, hi);
            sts32(sb + OFF2_AFL + o, lo);
        }
    }
    __syncthreads();

    // B-lo fragments for nfrags 0-1 -> registers (reads lo parts, post-sync)
    uint32_t blor[2][8][2];
    #pragma unroll
    for (int nf = 0; nf < 2; nf++)
        #pragma unroll
        for (int ks = 0; ks < 8; ks++)
            lds64(blor[nf][ks],
                  sb + OFF2_BLO + (((uint32_t)((wid * 4 + nf) * 8 + ks)) << 8) + (lane << 3));

    const int gate = wid >> 2;
    const int colb = ((wid & 3) << 5) + ((lane & 3) << 1);
    const int r1   = lane >> 2;

    for (int t = 0; t < TSTEPS; t++) {
        // ---- prefetch this step's pointwise operands ----
        {
            int nchunks = cnt * 96;
            for (int i = tid; i < nchunks; i += 384) {
                int rr = i / 96, q = i - rr * 96;
                size_t base = (size_t)(row0 + rr) * TSTEPS + t;
                cpa16(sb + OFF2_GXS + (uint32_t)(rr * GSTRIDE + q * 4) * 4,
                      g_G + base * GSTRIDE + q * 4);
            }
            if (tid < cnt) {
                size_t base = (size_t)(row0 + tid) * TSTEPS + t;
                cpa4(sb + OFF2_AS + tid * 4, inp + base * INSTRIDE + UDIM);
            }
            cpa_commit();
        }

        // ---- MMA phase: acc[16 x 32cols] = h @ U (3-pass split) ----
        float acc[4][4];
        #pragma unroll
        for (int nf = 0; nf < 4; nf++)
            #pragma unroll
            for (int q = 0; q < 4; q++) acc[nf][q] = 0.0f;

        #pragma unroll
        for (int ks = 0; ks < 8; ks++) {
            uint32_t Ah[4], Al[4];
            lds128(Ah, sb + OFF2_AFH + ks * 512 + lane * 16);
            lds128(Al, sb + OFF2_AFL + ks * 512 + lane * 16);
            #pragma unroll
            for (int nf = 0; nf < 2; nf++) {
                mma16816(acc[nf], Ah, bhi[nf][ks]);
                mma16816(acc[nf], Ah, blor[nf][ks]);
                mma16816(acc[nf], Al, bhi[nf][ks]);
            }
            #pragma unroll
            for (int nf = 2; nf < 4; nf++) {
                uint32_t Bl[2];
                lds64(Bl, sb + OFF2_BLO + (((uint32_t)((wid * 4 + nf) * 8 + ks)) << 8) + (lane << 3));
                mma16816(acc[nf], Ah, bhi[nf][ks]);
                mma16816(acc[nf], Ah, Bl);
                mma16816(acc[nf], Al, bhi[nf][ks]);
            }
        }

        // ---- scatter accs to smem (padded stride 132) ----
        #pragma unroll
        for (int nf = 0; nf < 4; nf++) {
            int colg = colb + (nf << 3);
            sts64f(sb + OFF2_ACC + (uint32_t)((gate * 16 + r1) * 132 + colg) * 4,
                   acc[nf][0], acc[nf][1]);
            sts64f(sb + OFF2_ACC + (uint32_t)((gate * 16 + r1 + 8) * 132 + colg) * 4,
                   acc[nf][2], acc[nf][3]);
        }
        cpa_wait0();
        __syncthreads();

        // ---- pointwise GRU update; h in regs; writes out + next A-frag ----
        #pragma unroll
        for (int i = 0; i < 3; i++) {
            int p = tid + i * 384;
            if (p < cnt * 64) {
                int r = p >> 6, u2 = (p & 63) << 1;
                size_t base = (size_t)(row0 + r) * TSTEPS + t;
                float2 xr = *(float2*)(gxs + r * GSTRIDE + u2);
                float2 xz = *(float2*)(gxs + r * GSTRIDE + UDIM + u2);
                float2 xh = *(float2*)(gxs + r * GSTRIDE + 2 * UDIM + u2);
                float  a  = as_s[r];
                float2 hp = hreg[i];

                float ar0 = accs[(r)      * 132 + u2], ar1 = accs[(r)      * 132 + u2 + 1];
                float az0 = accs[(16 + r) * 132 + u2], az1 = accs[(16 + r) * 132 + u2 + 1];
                float ah0 = accs[(32 + r) * 132 + u2], ah1 = accs[(32 + r) * 132 + u2 + 1];

                float rv0 = sigf(xr.x + ar0), rv1 = sigf(xr.y + ar1);
                float zv0 = sigf(xz.x + az0), zv1 = sigf(xz.y + az1);
                float ht0 = tanhfast(xh.x + rv0 * ah0);
                float ht1 = tanhfast(xh.y + rv1 * ah1);
                float u0 = a * zv0, u1 = a * zv1;
                float hn0 = (1.0f - u0) * hp.x + u0 * ht0;
                float hn1 = (1.0f - u1) * hp.y + u1 * ht1;

                *(float2*)(out + base * UDIM + u2) = make_float2(hn0, hn1);
                hreg[i] = make_float2(hn0, hn1);

                uint32_t hi, lo;
                split2(hn0, hn1, hi, lo);
                uint32_t o = afrag_off(r, u2);
                sts32(sb + OFF2_AFH + o, hi);
                sts32(sb + OFF2_AFL + o, lo);
            }
        }
        __syncthreads();
    }
}

// =====================================================================
// Probe: trivial third launch. Shifts which kernel the profiler's
// capture window lands on (3-launch pattern surfaced launch #1 = gemm).
// =====================================================================
__global__ void probe_k() {}

// =====================================================================
// Launch
// Inputs (metadata order): inputs, h0, W_r, U_r, b_r, W_z, U_z, b_z, W_h, U_h, b_h
// =====================================================================
extern "C" void kernel_launch(void* const* d_in, const int* in_sizes, int n_in,
                              void* d_out, int out_size)
{
    const float* inp = (const float*)d_in[0];
    const float* h0  = (const float*)d_in[1];
    const float* Wr  = (const float*)d_in[2];
    const float* Ur  = (const float*)d_in[3];
    const float* br  = (const float*)d_in[4];
    const float* Wz  = (const float*)d_in[5];
    const float* Uz  = (const float*)d_in[6];
    const float* bz  = (const float*)d_in[7];
    const float* Wh  = (const float*)d_in[8];
    const float* Uh  = (const float*)d_in[9];
    const float* bh  = (const float*)d_in[10];
    float* out = (float*)d_out;

    cudaFuncSetAttribute(gemm_tc, cudaFuncAttributeMaxDynamicSharedMemorySize, GM_SMEM);
    cudaFuncSetAttribute(gru_recur, cudaFuncAttributeMaxDynamicSharedMemorySize, SMEM2);

    gemm_tc<<<148, 256, GM_SMEM>>>(inp, Wr, Wz, Wh, br, bz, bh);
    gru_recur<<<148, 384, SMEM2>>>(inp, h0, Ur, Uz, Uh, out);
    probe_k<<<1, 1>>>();
}

// round 15
// speedup vs baseline: 1.5764x; 1.0194x over previous
#include <cuda_runtime.h>
#include <cuda_bf16.h>
#include <cstdint>

// Problem constants
#define TSTEPS   200
#define UDIM     128
#define BATCH    2048
#define MROWS    (BATCH * TSTEPS)     // 409600
#define GSTRIDE  384                  // xr|xz|xh concatenated
#define INSTRIDE 129                  // inputs last dim = U+1

// Scratch for precomputed input projections: 409600 x 384 fp32 = 629 MB
__device__ float g_G[157286400];      // MROWS * GSTRIDE

typedef unsigned long long ull;

// ---------------- fast activations ----------------
__device__ __forceinline__ float sigf(float x) {
    return __fdividef(1.0f, 1.0f + __expf(-x));
}
__device__ __forceinline__ float tanhfast(float x) {
    float e = __expf(-2.0f * fabsf(x));
    float t = __fdividef(1.0f - e, 1.0f + e);
    return copysignf(t, x);
}

// ---------------- cp.async helpers ----------------
__device__ __forceinline__ void cpa16(uint32_t saddr, const void* g) {
    asm volatile("cp.async.ca.shared.global [%0], [%1], 16;" :: "r"(saddr), "l"(g));
}
__device__ __forceinline__ void cpa4(uint32_t saddr, const void* g) {
    asm volatile("cp.async.ca.shared.global [%0], [%1], 4;" :: "r"(saddr), "l"(g));
}
__device__ __forceinline__ void cpa_commit() { asm volatile("cp.async.commit_group;"); }
__device__ __forceinline__ void cpa_wait0()  { asm volatile("cp.async.wait_group 0;"); }

// ---------------- mma.sync helpers ----------------
__device__ __forceinline__ void mma16816(float* c, const uint32_t* a, const uint32_t* b) {
    asm volatile(
        "mma.sync.aligned.m16n8k16.row.col.f32.bf16.bf16.f32 "
        "{%0,%1,%2,%3}, {%4,%5,%6,%7}, {%8,%9}, {%0,%1,%2,%3};"
        : "+f"(c[0]), "+f"(c[1]), "+f"(c[2]), "+f"(c[3])
        : "r"(a[0]), "r"(a[1]), "r"(a[2]), "r"(a[3]), "r"(b[0]), "r"(b[1]));
}
__device__ __forceinline__ void lds128(uint32_t* r, uint32_t addr) {
    asm volatile("ld.shared.v4.u32 {%0,%1,%2,%3}, [%4];"
        : "=r"(r[0]), "=r"(r[1]), "=r"(r[2]), "=r"(r[3]) : "r"(addr));
}
__device__ __forceinline__ void lds64(uint32_t* r, uint32_t addr) {
    asm volatile("ld.shared.v2.u32 {%0,%1}, [%2];"
        : "=r"(r[0]), "=r"(r[1]) : "r"(addr));
}
__device__ __forceinline__ void sts32(uint32_t addr, uint32_t v) {
    asm volatile("st.shared.u32 [%0], %1;" :: "r"(addr), "r"(v));
}
__device__ __forceinline__ void sts64f(uint32_t addr, float x, float y) {
    asm volatile("st.shared.v2.f32 [%0], {%1,%2};" :: "r"(addr), "f"(x), "f"(y));
}
// Split packed pair (x0, x1) into bf16x2 hi and lo parts. lo half of reg = x0.
__device__ __forceinline__ void split2(float x0, float x1, uint32_t& hi, uint32_t& lo) {
    asm("cvt.rn.bf16x2.f32 %0, %1, %2;" : "=r"(hi) : "f"(x1), "f"(x0));
    float h0 = __uint_as_float(hi << 16);
    float h1 = __uint_as_float(hi & 0xFFFF0000u);
    float l0 = x0 - h0;
    float l1 = x1 - h1;
    asm("cvt.rn.bf16x2.f32 %0, %1, %2;" : "=r"(lo) : "f"(l1), "f"(l0));
}

// =====================================================================
// Stage 1 (R13): 512-thread (16-warp) CTA, 128x128 tile, gate per CTA.
// Warp = (wm 0..7: one mfrag) x (wn 0..1: 8 nfrags). B hi/lo interleaved
// in one 16B/lane record -> single lds128 per (nf,ks). cp.async raw-X
// staging pipelined against the HMMA mainloop (R6 scheme).
// =====================================================================
#define OFF_AHI  0                     // 8 mfrag x 8 ks x 512B = 32768
#define OFF_ALO  32768
#define OFF_B    65536                 // 16 nfrag x 8 ks x 512B = 65536 (hi+lo interleaved)
#define OFF_BIAS 131072
#define OFF_RAW  131584
#define GM_SMEM  (OFF_RAW + 65536)     // 197120 bytes

__global__ void __launch_bounds__(512, 1) gemm_tc(
    const float* __restrict__ inp,
    const float* __restrict__ Wr, const float* __restrict__ Wz, const float* __restrict__ Wh,
    const float* __restrict__ br, const float* __restrict__ bz, const float* __restrict__ bh)
{
    extern __shared__ __align__(16) char smem[];
    const uint32_t sb = (uint32_t)__cvta_generic_to_shared(smem);
    float* bias_s = (float*)(smem + OFF_BIAS);
    const float* raws = (const float*)(smem + OFF_RAW);

    const int tid  = threadIdx.x;
    const int wid  = tid >> 5;
    const int lane = tid & 31;
    const int wm   = wid >> 1;            // 0..7 : mfrag (16 rows)
    const int wn   = wid & 1;             // 0..1 : 8 nfrags (64 cols)

    const int bid   = blockIdx.x;
    const int nblk  = bid % 3;
    const int start = bid / 3;
    const int mstride = (nblk == 0) ? 50 : 49;

    const float* Wg   = (nblk == 0) ? Wr : (nblk == 1) ? Wz : Wh;
    const float* bsrc = (nblk == 0) ? br : (nblk == 1) ? bz : bh;

    // ---- load + split W into interleaved B-fragment layout (once) ----
    // record: 512B per (nfrag,ks); lane l at +l*16: {hi_chi0, hi_chi1, lo_chi0, lo_chi1}
    {
        const int rbase = tid >> 6;       // 0..7
        const int kp    = tid & 63;
        const int ks  = kp >> 3;
        const int chi = (kp >> 2) & 1;
        #pragma unroll 4
        for (int j = 0; j < 16; j++) {
            int n = j * 8 + rbase;
            float w0 = Wg[(2 * kp) * UDIM + n];
            float w1 = Wg[(2 * kp + 1) * UDIM + n];
            uint32_t hi, lo;
            split2(w0, w1, hi, lo);
            int nfrag = n >> 3, nn = n & 7;
            uint32_t base = (uint32_t)((nfrag * 8 + ks) << 9) + ((nn * 4 + (kp & 3)) << 4);
            sts32(sb + OFF_B + base + (chi << 2), hi);
            sts32(sb + OFF_B + base + 8 + (chi << 2), lo);
        }
        if (tid < 128) bias_s[tid] = bsrc[tid];
    }

    // ---- prologue: prefetch first tile's raw X ----
    {
        const size_t m0 = (size_t)start * 128;
        #pragma unroll 4
        for (int j = 0; j < 32; j++) {
            int idx = j * 512 + tid;
            int row = idx >> 7, col = idx & 127;
            cpa4(sb + OFF_RAW + (uint32_t)idx * 4,
                 inp + (m0 + row) * INSTRIDE + col);
        }
    }
    cpa_commit();

    const int eg  = lane >> 2;
    const int et2 = (lane & 3) * 2;

    for (int mt = start; mt < 3200; mt += mstride) {
        const size_t m0 = (size_t)mt * 128;

        cpa_wait0();
        __syncthreads();

        // ---- convert raw X (smem) into A-fragment layout ----
        {
            const int rbase = tid >> 6;   // 0..7
            const int kp    = tid & 63;
            const int ks  = kp >> 3;
            const int t   = kp & 3;
            const int chi = (kp >> 2) & 1;
            #pragma unroll 4
            for (int j = 0; j < 16; j++) {
                int m = j * 8 + rbase;
                float2 x = *(const float2*)(raws + m * 128 + 2 * kp);
                uint32_t hi, lo;
                split2(x.x, x.y, hi, lo);
                int mfrag = m >> 4, r = m & 15, g2 = r & 7, rh = r >> 3;
                int lane_sw = (g2 * 4 + t) ^ ((ks & 3) << 1);
                uint32_t off = (uint32_t)((mfrag * 8 + ks) << 9) + (lane_sw << 4) + ((chi * 2 + rh) << 2);
                sts32(sb + OFF_AHI + off, hi);
                sts32(sb + OFF_ALO + off, lo);
            }
        }
        __syncthreads();

        // ---- prefetch next tile's raw X (overlaps mainloop) ----
        {
            int nmt = mt + mstride;
            if (nmt < 3200) {
                const size_t nm0 = (size_t)nmt * 128;
                #pragma unroll 4
                for (int j = 0; j < 32; j++) {
                    int idx = j * 512 + tid;
                    int row = idx >> 7, col = idx & 127;
                    cpa4(sb + OFF_RAW + (uint32_t)idx * 4,
                         inp + (nm0 + row) * INSTRIDE + col);
                }
            }
            cpa_commit();
        }

        // ---- mma mainloop: 1 mfrag x 8 nfrags per warp ----
        float acc[8][4];
        #pragma unroll
        for (int nf = 0; nf < 8; nf++)
            #pragma unroll
            for (int q = 0; q < 4; q++) acc[nf][q] = 0.0f;

        #pragma unroll 2
        for (int ks = 0; ks < 8; ks++) {
            const uint32_t asw = (uint32_t)((lane ^ ((ks & 3) << 1)) << 4);
            uint32_t Ahi[4], Alo[4];
            {
                uint32_t blk = (uint32_t)((wm * 8 + ks) << 9) + asw;
                lds128(Ahi, sb + OFF_AHI + blk);
                lds128(Alo, sb + OFF_ALO + blk);
            }
            #pragma unroll
            for (int nf = 0; nf < 8; nf++) {
                uint32_t B[4];   // {Bh0, Bh1, Bl0, Bl1}
                lds128(B, sb + OFF_B + (uint32_t)(((wn * 8 + nf) * 8 + ks) << 9) + (lane << 4));
                mma16816(acc[nf], Ahi, B);       // A_hi * B_hi
                mma16816(acc[nf], Ahi, B + 2);   // A_hi * B_lo
                mma16816(acc[nf], Alo, B);       // A_lo * B_hi
            }
        }

        // ---- epilogue: direct STG.64 ----
        {
            size_t row = m0 + wm * 16 + eg;
            #pragma unroll
            for (int nf = 0; nf < 8; nf++) {
                int coll = wn * 64 + nf * 8 + et2;
                float b0 = bias_s[coll], b1 = bias_s[coll + 1];
                float* gp = g_G + row * GSTRIDE + nblk * 128 + coll;
                float2 v0 = make_float2(acc[nf][0] + b0, acc[nf][1] + b1);
                float2 v1 = make_float2(acc[nf][2] + b0, acc[nf][3] + b1);
                *(float2*)gp = v0;
                *(float2*)(gp + 8 * GSTRIDE) = v1;
            }
        }
    }
}

// =====================================================================
// Stage 2: tensor-core recurrence (unchanged, measured 488us).
// =====================================================================
#define OFF2_BLO  0                    // 48 nfrags x 8 ks x 256B = 98304
#define OFF2_AFH  98304                // 8 ks x 32 lanes x 16B = 4096
#define OFF2_AFL  102400               // 4096
#define OFF2_ACC  106496               // 3*16*132*4 = 25344
#define OFF2_GXS  131840               // 14*384*4 = 21504
#define OFF2_AS   153344               // 64
#define SMEM2     153408

__device__ __forceinline__ uint32_t afrag_off(int r, int u2) {
    int ks   = u2 >> 4;
    int lane = ((r & 7) << 2) | ((u2 >> 1) & 3);
    int reg  = (r >> 3) | (((u2 >> 3) & 1) << 1);
    return (uint32_t)(ks * 512 + lane * 16 + reg * 4);
}

__global__ void __launch_bounds__(384, 1) gru_recur(
    const float* __restrict__ inp,
    const float* __restrict__ h0,
    const float* __restrict__ Ur, const float* __restrict__ Uz, const float* __restrict__ Uh,
    float* __restrict__ out)
{
    extern __shared__ __align__(16) char smem2[];
    const uint32_t sb = (uint32_t)__cvta_generic_to_shared(smem2);
    float* gxs  = (float*)(smem2 + OFF2_GXS);
    float* as_s = (float*)(smem2 + OFF2_AS);
    float* accs = (float*)(smem2 + OFF2_ACC);

    const int tid  = threadIdx.x;
    const int wid  = tid >> 5;
    const int lane = tid & 31;

    // Balanced row partition over 148 CTAs: 124x14 + 24x13 = 2048
    const int bid = blockIdx.x;
    int row0, cnt;
    if (bid < 124) { row0 = bid * 14;                    cnt = 14; }
    else           { row0 = 124 * 14 + (bid - 124) * 13; cnt = 13; }

    // zero A-frag regions (covers padded rows cnt..15 forever)
    for (int i = tid; i < 1024; i += 384) {
        ((uint32_t*)(smem2 + OFF2_AFH))[i] = 0;
        ((uint32_t*)(smem2 + OFF2_AFL))[i] = 0;
    }

    // ---- build B (U-cat) hi parts in frag layout ----
    for (int idx = tid; idx < 384 * 64; idx += 384) {
        int n = idx >> 6, kp = idx & 63;
        int g = n >> 7, col = n & 127;
        const float* Ug = (g == 0) ? Ur : (g == 1) ? Uz : Uh;
        float w0 = Ug[(2 * kp) * UDIM + col];
        float w1 = Ug[(2 * kp + 1) * UDIM + col];
        uint32_t hi, lo;
        split2(w0, w1, hi, lo);
        int nf48 = n >> 3, nn = n & 7, ks = kp >> 3, chi = (kp >> 2) & 1;
        uint32_t off = ((uint32_t)(nf48 * 8 + ks) << 8) + ((nn * 4 + (kp & 3)) << 3) + (chi << 2);
        sts32(sb + OFF2_BLO + off, hi);
    }
    __syncthreads();

    // each warp loads its resident B-hi fragments (64 regs)
    uint32_t bhi[4][8][2];
    #pragma unroll
    for (int nf = 0; nf < 4; nf++)
        #pragma unroll
        for (int ks = 0; ks < 8; ks++)
            lds64(bhi[nf][ks],
                  sb + OFF2_BLO + (((uint32_t)((wid * 4 + nf) * 8 + ks)) << 8) + (lane << 3));
    __syncthreads();

    // ---- overwrite B region with lo parts ----
    for (int idx = tid; idx < 384 * 64; idx += 384) {
        int n = idx >> 6, kp = idx & 63;
        int g = n >> 7, col = n & 127;
        const float* Ug = (g == 0) ? Ur : (g == 1) ? Uz : Uh;
        float w0 = Ug[(2 * kp) * UDIM + col];
        float w1 = Ug[(2 * kp + 1) * UDIM + col];
        uint32_t hi, lo;
        split2(w0, w1, hi, lo);
        int nf48 = n >> 3, nn = n & 7, ks = kp >> 3, chi = (kp >> 2) & 1;
        uint32_t off = ((uint32_t)(nf48 * 8 + ks) << 8) + ((nn * 4 + (kp & 3)) << 3) + (chi << 2);
        sts32(sb + OFF2_BLO + off, lo);
    }

    // ---- h state -> registers; initial A-frag from h0 ----
    float2 hreg[3];
    #pragma unroll
    for (int i = 0; i < 3; i++) {
        int p = tid + i * 384;
        if (p < cnt * 64) {
            int r = p >> 6, u2 = (p & 63) << 1;
            hreg[i] = *(const float2*)(h0 + (size_t)(row0 + r) * UDIM + u2);
            uint32_t hi, lo;
            split2(hreg[i].x, hreg[i].y, hi, lo);
            uint32_t o = afrag_off(r, u2);
            sts32(sb + OFF2_AFH + o, hi);
            sts32(sb + OFF2_AFL + o, lo);
        }
    }
    __syncthreads();

    // B-lo fragments for nfrags 0-1 -> registers (reads lo parts, post-sync)
    uint32_t blor[2][8][2];
    #pragma unroll
    for (int nf = 0; nf < 2; nf++)
        #pragma unroll
        for (int ks = 0; ks < 8; ks++)
            lds64(blor[nf][ks],
                  sb + OFF2_BLO + (((uint32_t)((wid * 4 + nf) * 8 + ks)) << 8) + (lane << 3));

    const int gate = wid >> 2;
    const int colb = ((wid & 3) << 5) + ((lane & 3) << 1);
    const int r1   = lane >> 2;

    for (int t = 0; t < TSTEPS; t++) {
        // ---- prefetch this step's pointwise operands ----
        {
            int nchunks = cnt * 96;
            for (int i = tid; i < nchunks; i += 384) {
                int rr = i / 96, q = i - rr * 96;
                size_t base = (size_t)(row0 + rr) * TSTEPS + t;
                cpa16(sb + OFF2_GXS + (uint32_t)(rr * GSTRIDE + q * 4) * 4,
                      g_G + base * GSTRIDE + q * 4);
            }
            if (tid < cnt) {
                size_t base = (size_t)(row0 + tid) * TSTEPS + t;
                cpa4(sb + OFF2_AS + tid * 4, inp + base * INSTRIDE + UDIM);
            }
            cpa_commit();
        }

        // ---- MMA phase: acc[16 x 32cols] = h @ U (3-pass split) ----
        float acc[4][4];
        #pragma unroll
        for (int nf = 0; nf < 4; nf++)
            #pragma unroll
            for (int q = 0; q < 4; q++) acc[nf][q] = 0.0f;

        #pragma unroll
        for (int ks = 0; ks < 8; ks++) {
            uint32_t Ah[4], Al[4];
            lds128(Ah, sb + OFF2_AFH + ks * 512 + lane * 16);
            lds128(Al, sb + OFF2_AFL + ks * 512 + lane * 16);
            #pragma unroll
            for (int nf = 0; nf < 2; nf++) {
                mma16816(acc[nf], Ah, bhi[nf][ks]);
                mma16816(acc[nf], Ah, blor[nf][ks]);
                mma16816(acc[nf], Al, bhi[nf][ks]);
            }
            #pragma unroll
            for (int nf = 2; nf < 4; nf++) {
                uint32_t Bl[2];
                lds64(Bl, sb + OFF2_BLO + (((uint32_t)((wid * 4 + nf) * 8 + ks)) << 8) + (lane << 3));
                mma16816(acc[nf], Ah, bhi[nf][ks]);
                mma16816(acc[nf], Ah, Bl);
                mma16816(acc[nf], Al, bhi[nf][ks]);
            }
        }

        // ---- scatter accs to smem (padded stride 132) ----
        #pragma unroll
        for (int nf = 0; nf < 4; nf++) {
            int colg = colb + (nf << 3);
            sts64f(sb + OFF2_ACC + (uint32_t)((gate * 16 + r1) * 132 + colg) * 4,
                   acc[nf][0], acc[nf][1]);
            sts64f(sb + OFF2_ACC + (uint32_t)((gate * 16 + r1 + 8) * 132 + colg) * 4,
                   acc[nf][2], acc[nf][3]);
        }
        cpa_wait0();
        __syncthreads();

        // ---- pointwise GRU update; h in regs; writes out + next A-frag ----
        #pragma unroll
        for (int i = 0; i < 3; i++) {
            int p = tid + i * 384;
            if (p < cnt * 64) {
                int r = p >> 6, u2 = (p & 63) << 1;
                size_t base = (size_t)(row0 + r) * TSTEPS + t;
                float2 xr = *(float2*)(gxs + r * GSTRIDE + u2);
                float2 xz = *(float2*)(gxs + r * GSTRIDE + UDIM + u2);
                float2 xh = *(float2*)(gxs + r * GSTRIDE + 2 * UDIM + u2);
                float  a  = as_s[r];
                float2 hp = hreg[i];

                float ar0 = accs[(r)      * 132 + u2], ar1 = accs[(r)      * 132 + u2 + 1];
                float az0 = accs[(16 + r) * 132 + u2], az1 = accs[(16 + r) * 132 + u2 + 1];
                float ah0 = accs[(32 + r) * 132 + u2], ah1 = accs[(32 + r) * 132 + u2 + 1];

                float rv0 = sigf(xr.x + ar0), rv1 = sigf(xr.y + ar1);
                float zv0 = sigf(xz.x + az0), zv1 = sigf(xz.y + az1);
                float ht0 = tanhfast(xh.x + rv0 * ah0);
                float ht1 = tanhfast(xh.y + rv1 * ah1);
                float u0 = a * zv0, u1 = a * zv1;
                float hn0 = (1.0f - u0) * hp.x + u0 * ht0;
                float hn1 = (1.0f - u1) * hp.y + u1 * ht1;

                *(float2*)(out + base * UDIM + u2) = make_float2(hn0, hn1);
                hreg[i] = make_float2(hn0, hn1);

                uint32_t hi, lo;
                split2(hn0, hn1, hi, lo);
                uint32_t o = afrag_off(r, u2);
                sts32(sb + OFF2_AFH + o, hi);
                sts32(sb + OFF2_AFL + o, lo);
            }
        }
        __syncthreads();
    }
}

// =====================================================================
// Probe: trivial third launch so the profiler window surfaces gemm_tc.
// =====================================================================
__global__ void probe_k() {}

// =====================================================================
// Launch
// Inputs (metadata order): inputs, h0, W_r, U_r, b_r, W_z, U_z, b_z, W_h, U_h, b_h
// =====================================================================
extern "C" void kernel_launch(void* const* d_in, const int* in_sizes, int n_in,
                              void* d_out, int out_size)
{
    const float* inp = (const float*)d_in[0];
    const float* h0  = (const float*)d_in[1];
    const float* Wr  = (const float*)d_in[2];
    const float* Ur  = (const float*)d_in[3];
    const float* br  = (const float*)d_in[4];
    const float* Wz  = (const float*)d_in[5];
    const float* Uz  = (const float*)d_in[6];
    const float* bz  = (const float*)d_in[7];
    const float* Wh  = (const float*)d_in[8];
    const float* Uh  = (const float*)d_in[9];
    const float* bh  = (const float*)d_in[10];
    float* out = (float*)d_out;

    cudaFuncSetAttribute(gemm_tc, cudaFuncAttributeMaxDynamicSharedMemorySize, GM_SMEM);
    cudaFuncSetAttribute(gru_recur, cudaFuncAttributeMaxDynamicSharedMemorySize, SMEM2);

    gemm_tc<<<148, 512, GM_SMEM>>>(inp, Wr, Wz, Wh, br, bz, bh);
    gru_recur<<<148, 384, SMEM2>>>(inp, h0, Ur, Uz, Uh, out);
    probe_k<<<1, 1>>>();
}

// round 16
// speedup vs baseline: 1.6083x; 1.0203x over previous
#include <cuda_runtime.h>
#include <cuda_bf16.h>
#include <cstdint>

// Problem constants
#define TSTEPS   200
#define UDIM     128
#define BATCH    2048
#define MROWS    (BATCH * TSTEPS)     // 409600
#define GSTRIDE  384                  // xr|xz|xh concatenated
#define INSTRIDE 129                  // inputs last dim = U+1

// Scratch for precomputed input projections: 409600 x 384 fp32 = 629 MB
__device__ float g_G[157286400];      // MROWS * GSTRIDE

typedef unsigned long long ull;

// ---------------- fast activations ----------------
__device__ __forceinline__ float sigf(float x) {
    return __fdividef(1.0f, 1.0f + __expf(-x));
}
__device__ __forceinline__ float tanhfast(float x) {
    float e = __expf(-2.0f * fabsf(x));
    float t = __fdividef(1.0f - e, 1.0f + e);
    return copysignf(t, x);
}

// ---------------- cp.async helpers ----------------
__device__ __forceinline__ void cpa16(uint32_t saddr, const void* g) {
    asm volatile("cp.async.ca.shared.global [%0], [%1], 16;" :: "r"(saddr), "l"(g));
}
__device__ __forceinline__ void cpa4(uint32_t saddr, const void* g) {
    asm volatile("cp.async.ca.shared.global [%0], [%1], 4;" :: "r"(saddr), "l"(g));
}
__device__ __forceinline__ void cpa_commit() { asm volatile("cp.async.commit_group;"); }
__device__ __forceinline__ void cpa_wait0()  { asm volatile("cp.async.wait_group 0;"); }

// ---------------- mma.sync helpers ----------------
__device__ __forceinline__ void mma16816(float* c, const uint32_t* a, const uint32_t* b) {
    asm volatile(
        "mma.sync.aligned.m16n8k16.row.col.f32.bf16.bf16.f32 "
        "{%0,%1,%2,%3}, {%4,%5,%6,%7}, {%8,%9}, {%0,%1,%2,%3};"
        : "+f"(c[0]), "+f"(c[1]), "+f"(c[2]), "+f"(c[3])
        : "r"(a[0]), "r"(a[1]), "r"(a[2]), "r"(a[3]), "r"(b[0]), "r"(b[1]));
}
__device__ __forceinline__ void lds128(uint32_t* r, uint32_t addr) {
    asm volatile("ld.shared.v4.u32 {%0,%1,%2,%3}, [%4];"
        : "=r"(r[0]), "=r"(r[1]), "=r"(r[2]), "=r"(r[3]) : "r"(addr));
}
__device__ __forceinline__ void lds64(uint32_t* r, uint32_t addr) {
    asm volatile("ld.shared.v2.u32 {%0,%1}, [%2];"
        : "=r"(r[0]), "=r"(r[1]) : "r"(addr));
}
__device__ __forceinline__ void sts32(uint32_t addr, uint32_t v) {
    asm volatile("st.shared.u32 [%0], %1;" :: "r"(addr), "r"(v));
}
__device__ __forceinline__ void sts64f(uint32_t addr, float x, float y) {
    asm volatile("st.shared.v2.f32 [%0], {%1,%2};" :: "r"(addr), "f"(x), "f"(y));
}
// Split packed pair (x0, x1) into bf16x2 hi and lo parts. lo half of reg = x0.
__device__ __forceinline__ void split2(float x0, float x1, uint32_t& hi, uint32_t& lo) {
    asm("cvt.rn.bf16x2.f32 %0, %1, %2;" : "=r"(hi) : "f"(x1), "f"(x0));
    float h0 = __uint_as_float(hi << 16);
    float h1 = __uint_as_float(hi & 0xFFFF0000u);
    float l0 = x0 - h0;
    float l1 = x1 - h1;
    asm("cvt.rn.bf16x2.f32 %0, %1, %2;" : "=r"(lo) : "f"(l1), "f"(l0));
}

// =====================================================================
// Stage 1 (R15): 512-thread CTA, 128x128 tile, gate per CTA.
// Warp grid 4x4: warp = 2 mfrags x 4 nfrags (8 lds128 per warp per ks
// for 24 HMMA, was 10). Raw X staged via ALIGNED cpa16 windows
// (33 x 16B per row, stride-132 smem rows, head offset row&3):
// 132 warp-LSU ops/tile instead of 512.
// =====================================================================
#define OFF_AHI  0                     // 8 mfrag x 8 ks x 512B = 32768
#define OFF_ALO  32768
#define OFF_B    65536                 // 16 nfrag x 8 ks x 512B (hi/lo interleaved)
#define OFF_BIAS 131072
#define OFF_RAW  131584                // 128 rows x 132 floats = 67584
#define GM_SMEM  (OFF_RAW + 128 * 132 * 4)   // 199168 bytes

__global__ void __launch_bounds__(512, 1) gemm_tc(
    const float* __restrict__ inp,
    const float* __restrict__ Wr, const float* __restrict__ Wz, const float* __restrict__ Wh,
    const float* __restrict__ br, const float* __restrict__ bz, const float* __restrict__ bh)
{
    extern __shared__ __align__(16) char smem[];
    const uint32_t sb = (uint32_t)__cvta_generic_to_shared(smem);
    float* bias_s = (float*)(smem + OFF_BIAS);
    const float* raws = (const float*)(smem + OFF_RAW);

    const int tid  = threadIdx.x;
    const int wid  = tid >> 5;
    const int lane = tid & 31;
    const int wm   = wid >> 2;            // 0..3 : pair of mfrags (32 rows)
    const int wn   = wid & 3;             // 0..3 : 4 nfrags (32 cols)

    const int bid   = blockIdx.x;
    const int nblk  = bid % 3;
    const int start = bid / 3;
    const int mstride = (nblk == 0) ? 50 : 49;

    const float* Wg   = (nblk == 0) ? Wr : (nblk == 1) ? Wz : Wh;
    const float* bsrc = (nblk == 0) ? br : (nblk == 1) ? bz : bh;

    // ---- load + split W into interleaved B-fragment layout (once) ----
    {
        const int rbase = tid >> 6;       // 0..7
        const int kp    = tid & 63;
        const int ks  = kp >> 3;
        const int chi = (kp >> 2) & 1;
        #pragma unroll 4
        for (int j = 0; j < 16; j++) {
            int n = j * 8 + rbase;
            float w0 = Wg[(2 * kp) * UDIM + n];
            float w1 = Wg[(2 * kp + 1) * UDIM + n];
            uint32_t hi, lo;
            split2(w0, w1, hi, lo);
            int nfrag = n >> 3, nn = n & 7;
            uint32_t base = (uint32_t)((nfrag * 8 + ks) << 9) + ((nn * 4 + (kp & 3)) << 4);
            sts32(sb + OFF_B + base + (chi << 2), hi);
            sts32(sb + OFF_B + base + 8 + (chi << 2), lo);
        }
        if (tid < 128) bias_s[tid] = bsrc[tid];
    }

    // ---- prologue: prefetch first tile's raw X (aligned 16B windows) ----
    {
        const size_t m0 = (size_t)start * 128;
        for (int idx = tid; idx < 128 * 33; idx += 512) {
            int row = idx / 33, chunk = idx - row * 33;
            if (chunk < 32 || (row & 3)) {
                cpa16(sb + OFF_RAW + (uint32_t)(row * 132 + chunk * 4) * 4,
                      inp + (size_t)(m0 + row) * INSTRIDE - (row & 3) + chunk * 4);
            }
        }
    }
    cpa_commit();

    const int eg  = lane >> 2;
    const int et2 = (lane & 3) * 2;

    for (int mt = start; mt < 3200; mt += mstride) {
        const size_t m0 = (size_t)mt * 128;

        cpa_wait0();
        __syncthreads();

        // ---- convert raw X (smem, head offset row&3) into A-frag layout ----
        {
            const int rbase = tid >> 6;   // 0..7
            const int kp    = tid & 63;
            const int ks  = kp >> 3;
            const int t   = kp & 3;
            const int chi = (kp >> 2) & 1;
            #pragma unroll 4
            for (int j = 0; j < 16; j++) {
                int m = j * 8 + rbase;
                const float* pr = raws + m * 132 + (m & 3) + 2 * kp;
                float x0 = pr[0];
                float x1 = pr[1];
                uint32_t hi, lo;
                split2(x0, x1, hi, lo);
                int mfrag = m >> 4, r = m & 15, g2 = r & 7, rh = r >> 3;
                int lane_sw = (g2 * 4 + t) ^ ((ks & 3) << 1);
                uint32_t off = (uint32_t)((mfrag * 8 + ks) << 9) + (lane_sw << 4) + ((chi * 2 + rh) << 2);
                sts32(sb + OFF_AHI + off, hi);
                sts32(sb + OFF_ALO + off, lo);
            }
        }
        __syncthreads();

        // ---- prefetch next tile's raw X (overlaps mainloop) ----
        {
            int nmt = mt + mstride;
            if (nmt < 3200) {
                const size_t nm0 = (size_t)nmt * 128;
                for (int idx = tid; idx < 128 * 33; idx += 512) {
                    int row = idx / 33, chunk = idx - row * 33;
                    if (chunk < 32 || (row & 3)) {
                        cpa16(sb + OFF_RAW + (uint32_t)(row * 132 + chunk * 4) * 4,
                              inp + (size_t)(nm0 + row) * INSTRIDE - (row & 3) + chunk * 4);
                    }
                }
            }
            cpa_commit();
        }

        // ---- mma mainloop: 2 mfrags x 4 nfrags per warp ----
        float acc[2][4][4];
        #pragma unroll
        for (int mf = 0; mf < 2; mf++)
            #pragma unroll
            for (int nf = 0; nf < 4; nf++)
                #pragma unroll
                for (int q = 0; q < 4; q++) acc[mf][nf][q] = 0.0f;

        #pragma unroll 2
        for (int ks = 0; ks < 8; ks++) {
            const uint32_t asw = (uint32_t)((lane ^ ((ks & 3) << 1)) << 4);
            uint32_t Ahi[2][4], Alo[2][4];
            #pragma unroll
            for (int mf = 0; mf < 2; mf++) {
                uint32_t blk = (uint32_t)(((wm * 2 + mf) * 8 + ks) << 9) + asw;
                lds128(Ahi[mf], sb + OFF_AHI + blk);
                lds128(Alo[mf], sb + OFF_ALO + blk);
            }
            #pragma unroll
            for (int nf = 0; nf < 4; nf++) {
                uint32_t B[4];   // {Bh0, Bh1, Bl0, Bl1}
                lds128(B, sb + OFF_B + (uint32_t)(((wn * 4 + nf) * 8 + ks) << 9) + (lane << 4));
                #pragma unroll
                for (int mf = 0; mf < 2; mf++) {
                    mma16816(acc[mf][nf], Ahi[mf], B);       // A_hi * B_hi
                    mma16816(acc[mf][nf], Ahi[mf], B + 2);   // A_hi * B_lo
                    mma16816(acc[mf][nf], Alo[mf], B);       // A_lo * B_hi
                }
            }
        }

        // ---- epilogue: direct STG.64 ----
        #pragma unroll
        for (int mf = 0; mf < 2; mf++) {
            size_t row = m0 + (wm * 2 + mf) * 16 + eg;
            #pragma unroll
            for (int nf = 0; nf < 4; nf++) {
                int coll = (wn * 4 + nf) * 8 + et2;
                float b0 = bias_s[coll], b1 = bias_s[coll + 1];
                float* gp = g_G + row * GSTRIDE + nblk * 128 + coll;
                float2 v0 = make_float2(acc[mf][nf][0] + b0, acc[mf][nf][1] + b1);
                float2 v1 = make_float2(acc[mf][nf][2] + b0, acc[mf][nf][3] + b1);
                *(float2*)gp = v0;
                *(float2*)(gp + 8 * GSTRIDE) = v1;
            }
        }
    }
}

// =====================================================================
// Stage 2: tensor-core recurrence (unchanged, measured 488us).
// =====================================================================
#define OFF2_BLO  0                    // 48 nfrags x 8 ks x 256B = 98304
#define OFF2_AFH  98304                // 8 ks x 32 lanes x 16B = 4096
#define OFF2_AFL  102400               // 4096
#define OFF2_ACC  106496               // 3*16*132*4 = 25344
#define OFF2_GXS  131840               // 14*384*4 = 21504
#define OFF2_AS   153344               // 64
#define SMEM2     153408

__device__ __forceinline__ uint32_t afrag_off(int r, int u2) {
    int ks   = u2 >> 4;
    int lane = ((r & 7) << 2) | ((u2 >> 1) & 3);
    int reg  = (r >> 3) | (((u2 >> 3) & 1) << 1);
    return (uint32_t)(ks * 512 + lane * 16 + reg * 4);
}

__global__ void __launch_bounds__(384, 1) gru_recur(
    const float* __restrict__ inp,
    const float* __restrict__ h0,
    const float* __restrict__ Ur, const float* __restrict__ Uz, const float* __restrict__ Uh,
    float* __restrict__ out)
{
    extern __shared__ __align__(16) char smem2[];
    const uint32_t sb = (uint32_t)__cvta_generic_to_shared(smem2);
    float* gxs  = (float*)(smem2 + OFF2_GXS);
    float* as_s = (float*)(smem2 + OFF2_AS);
    float* accs = (float*)(smem2 + OFF2_ACC);

    const int tid  = threadIdx.x;
    const int wid  = tid >> 5;
    const int lane = tid & 31;

    // Balanced row partition over 148 CTAs: 124x14 + 24x13 = 2048
    const int bid = blockIdx.x;
    int row0, cnt;
    if (bid < 124) { row0 = bid * 14;                    cnt = 14; }
    else           { row0 = 124 * 14 + (bid - 124) * 13; cnt = 13; }

    // zero A-frag regions (covers padded rows cnt..15 forever)
    for (int i = tid; i < 1024; i += 384) {
        ((uint32_t*)(smem2 + OFF2_AFH))[i] = 0;
        ((uint32_t*)(smem2 + OFF2_AFL))[i] = 0;
    }

    // ---- build B (U-cat) hi parts in frag layout ----
    for (int idx = tid; idx < 384 * 64; idx += 384) {
        int n = idx >> 6, kp = idx & 63;
        int g = n >> 7, col = n & 127;
        const float* Ug = (g == 0) ? Ur : (g == 1) ? Uz : Uh;
        float w0 = Ug[(2 * kp) * UDIM + col];
        float w1 = Ug[(2 * kp + 1) * UDIM + col];
        uint32_t hi, lo;
        split2(w0, w1, hi, lo);
        int nf48 = n >> 3, nn = n & 7, ks = kp >> 3, chi = (kp >> 2) & 1;
        uint32_t off = ((uint32_t)(nf48 * 8 + ks) << 8) + ((nn * 4 + (kp & 3)) << 3) + (chi << 2);
        sts32(sb + OFF2_BLO + off, hi);
    }
    __syncthreads();

    // each warp loads its resident B-hi fragments (64 regs)
    uint32_t bhi[4][8][2];
    #pragma unroll
    for (int nf = 0; nf < 4; nf++)
        #pragma unroll
        for (int ks = 0; ks < 8; ks++)
            lds64(bhi[nf][ks],
                  sb + OFF2_BLO + (((uint32_t)((wid * 4 + nf) * 8 + ks)) << 8) + (lane << 3));
    __syncthreads();

    // ---- overwrite B region with lo parts ----
    for (int idx = tid; idx < 384 * 64; idx += 384) {
        int n = idx >> 6, kp = idx & 63;
        int g = n >> 7, col = n & 127;
        const float* Ug = (g == 0) ? Ur : (g == 1) ? Uz : Uh;
        float w0 = Ug[(2 * kp) * UDIM + col];
        float w1 = Ug[(2 * kp + 1) * UDIM + col];
        uint32_t hi, lo;
        split2(w0, w1, hi, lo);
        int nf48 = n >> 3, nn = n & 7, ks = kp >> 3, chi = (kp >> 2) & 1;
        uint32_t off = ((uint32_t)(nf48 * 8 + ks) << 8) + ((nn * 4 + (kp & 3)) << 3) + (chi << 2);
        sts32(sb + OFF2_BLO + off, lo);
    }

    // ---- h state -> registers; initial A-frag from h0 ----
    float2 hreg[3];
    #pragma unroll
    for (int i = 0; i < 3; i++) {
        int p = tid + i * 384;
        if (p < cnt * 64) {
            int r = p >> 6, u2 = (p & 63) << 1;
            hreg[i] = *(const float2*)(h0 + (size_t)(row0 + r) * UDIM + u2);
            uint32_t hi, lo;
            split2(hreg[i].x, hreg[i].y, hi, lo);
            uint32_t o = afrag_off(r, u2);
            sts32(sb + OFF2_AFH + o, hi);
            sts32(sb + OFF2_AFL + o, lo);
        }
    }
    __syncthreads();

    // B-lo fragments for nfrags 0-1 -> registers (reads lo parts, post-sync)
    uint32_t blor[2][8][2];
    #pragma unroll
    for (int nf = 0; nf < 2; nf++)
        #pragma unroll
        for (int ks = 0; ks < 8; ks++)
            lds64(blor[nf][ks],
                  sb + OFF2_BLO + (((uint32_t)((wid * 4 + nf) * 8 + ks)) << 8) + (lane << 3));

    const int gate = wid >> 2;
    const int colb = ((wid & 3) << 5) + ((lane & 3) << 1);
    const int r1   = lane >> 2;

    for (int t = 0; t < TSTEPS; t++) {
        // ---- prefetch this step's pointwise operands ----
        {
            int nchunks = cnt * 96;
            for (int i = tid; i < nchunks; i += 384) {
                int rr = i / 96, q = i - rr * 96;
                size_t base = (size_t)(row0 + rr) * TSTEPS + t;
                cpa16(sb + OFF2_GXS + (uint32_t)(rr * GSTRIDE + q * 4) * 4,
                      g_G + base * GSTRIDE + q * 4);
            }
            if (tid < cnt) {
                size_t base = (size_t)(row0 + tid) * TSTEPS + t;
                cpa4(sb + OFF2_AS + tid * 4, inp + base * INSTRIDE + UDIM);
            }
            cpa_commit();
        }

        // ---- MMA phase: acc[16 x 32cols] = h @ U (3-pass split) ----
        float acc[4][4];
        #pragma unroll
        for (int nf = 0; nf < 4; nf++)
            #pragma unroll
            for (int q = 0; q < 4; q++) acc[nf][q] = 0.0f;

        #pragma unroll
        for (int ks = 0; ks < 8; ks++) {
            uint32_t Ah[4], Al[4];
            lds128(Ah, sb + OFF2_AFH + ks * 512 + lane * 16);
            lds128(Al, sb + OFF2_AFL + ks * 512 + lane * 16);
            #pragma unroll
            for (int nf = 0; nf < 2; nf++) {
                mma16816(acc[nf], Ah, bhi[nf][ks]);
                mma16816(acc[nf], Ah, blor[nf][ks]);
                mma16816(acc[nf], Al, bhi[nf][ks]);
            }
            #pragma unroll
            for (int nf = 2; nf < 4; nf++) {
                uint32_t Bl[2];
                lds64(Bl, sb + OFF2_BLO + (((uint32_t)((wid * 4 + nf) * 8 + ks)) << 8) + (lane << 3));
                mma16816(acc[nf], Ah, bhi[nf][ks]);
                mma16816(acc[nf], Ah, Bl);
                mma16816(acc[nf], Al, bhi[nf][ks]);
            }
        }

        // ---- scatter accs to smem (padded stride 132) ----
        #pragma unroll
        for (int nf = 0; nf < 4; nf++) {
            int colg = colb + (nf << 3);
            sts64f(sb + OFF2_ACC + (uint32_t)((gate * 16 + r1) * 132 + colg) * 4,
                   acc[nf][0], acc[nf][1]);
            sts64f(sb + OFF2_ACC + (uint32_t)((gate * 16 + r1 + 8) * 132 + colg) * 4,
                   acc[nf][2], acc[nf][3]);
        }
        cpa_wait0();
        __syncthreads();

        // ---- pointwise GRU update; h in regs; writes out + next A-frag ----
        #pragma unroll
        for (int i = 0; i < 3; i++) {
            int p = tid + i * 384;
            if (p < cnt * 64) {
                int r = p >> 6, u2 = (p & 63) << 1;
                size_t base = (size_t)(row0 + r) * TSTEPS + t;
                float2 xr = *(float2*)(gxs + r * GSTRIDE + u2);
                float2 xz = *(float2*)(gxs + r * GSTRIDE + UDIM + u2);
                float2 xh = *(float2*)(gxs + r * GSTRIDE + 2 * UDIM + u2);
                float  a  = as_s[r];
                float2 hp = hreg[i];

                float ar0 = accs[(r)      * 132 + u2], ar1 = accs[(r)      * 132 + u2 + 1];
                float az0 = accs[(16 + r) * 132 + u2], az1 = accs[(16 + r) * 132 + u2 + 1];
                float ah0 = accs[(32 + r) * 132 + u2], ah1 = accs[(32 + r) * 132 + u2 + 1];

                float rv0 = sigf(xr.x + ar0), rv1 = sigf(xr.y + ar1);
                float zv0 = sigf(xz.x + az0), zv1 = sigf(xz.y + az1);
                float ht0 = tanhfast(xh.x + rv0 * ah0);
                float ht1 = tanhfast(xh.y + rv1 * ah1);
                float u0 = a * zv0, u1 = a * zv1;
                float hn0 = (1.0f - u0) * hp.x + u0 * ht0;
                float hn1 = (1.0f - u1) * hp.y + u1 * ht1;

                *(float2*)(out + base * UDIM + u2) = make_float2(hn0, hn1);
                hreg[i] = make_float2(hn0, hn1);

                uint32_t hi, lo;
                split2(hn0, hn1, hi, lo);
                uint32_t o = afrag_off(r, u2);
                sts32(sb + OFF2_AFH + o, hi);
                sts32(sb + OFF2_AFL + o, lo);
            }
        }
        __syncthreads();
    }
}

// =====================================================================
// Probe: trivial third launch so the profiler window surfaces gemm_tc.
// =====================================================================
__global__ void probe_k() {}

// =====================================================================
// Launch
// Inputs (metadata order): inputs, h0, W_r, U_r, b_r, W_z, U_z, b_z, W_h, U_h, b_h
// =====================================================================
extern "C" void kernel_launch(void* const* d_in, const int* in_sizes, int n_in,
                              void* d_out, int out_size)
{
    const float* inp = (const float*)d_in[0];
    const float* h0  = (const float*)d_in[1];
    const float* Wr  = (const float*)d_in[2];
    const float* Ur  = (const float*)d_in[3];
    const float* br  = (const float*)d_in[4];
    const float* Wz  = (const float*)d_in[5];
    const float* Uz  = (const float*)d_in[6];
    const float* bz  = (const float*)d_in[7];
    const float* Wh  = (const float*)d_in[8];
    const float* Uh  = (const float*)d_in[9];
    const float* bh  = (const float*)d_in[10];
    float* out = (float*)d_out;

    cudaFuncSetAttribute(gemm_tc, cudaFuncAttributeMaxDynamicSharedMemorySize, GM_SMEM);
    cudaFuncSetAttribute(gru_recur, cudaFuncAttributeMaxDynamicSharedMemorySize, SMEM2);

    gemm_tc<<<148, 512, GM_SMEM>>>(inp, Wr, Wz, Wh, br, bz, bh);
    gru_recur<<<148, 384, SMEM2>>>(inp, h0, Ur, Uz, Uh, out);
    probe_k<<<1, 1>>>();
}